// round 9
// baseline (speedup 1.0000x reference)
#include <cuda_runtime.h>
#include <utility>
#include <cstddef>

// ============================================================================
// Compile-time Clifford algebra tables for N_GEN = 6 (DIM = 64).
// ============================================================================

struct Alg {
    int blade[64];
    int cls[64];
    signed char ktab[64][64];   // [j][i] -> k
    signed char sgn[64][64];    // [j][i] -> 1 if negative
    signed char ptab[64][64];   // [j][i] -> w_gp column p
    int P;
};

constexpr int popc6(int x) { int c = 0; for (int b = 0; b < 6; ++b) c += (x >> b) & 1; return c; }

constexpr Alg make_alg() {
    Alg a{};
    int idx = 0;
    for (int g = 0; g <= 6; ++g)
        for (int b = 0; b < 64; ++b)
            if (popc6(b) == g) a.blade[idx++] = b;
    int inv[64] = {};
    for (int i = 0; i < 64; ++i) inv[a.blade[i]] = i;
    for (int i = 0; i < 64; ++i) a.cls[i] = popc6(a.blade[i]) & 3;

    bool paths[64] = {};
    for (int i = 0; i < 64; ++i)
        for (int k = 0; k < 64; ++k) {
            int j = inv[a.blade[i] ^ a.blade[k]];
            paths[a.cls[i] * 16 + a.cls[j] * 4 + a.cls[k]] = true;
        }
    int pmap[64] = {};
    int P = 0;
    for (int t = 0; t < 64; ++t) pmap[t] = paths[t] ? P++ : -1;
    a.P = P;

    for (int j = 0; j < 64; ++j)
        for (int i = 0; i < 64; ++i) {
            int bi = a.blade[i], bj = a.blade[j];
            int bk = bi ^ bj;
            int k = inv[bk];
            a.ktab[j][i] = (signed char)k;
            int s = 0;
            int t = bi >> 1;
            while (t) { s += popc6(t & bk); t >>= 1; }
            a.sgn[j][i] = (signed char)(s & 1);
            a.ptab[j][i] = (signed char)pmap[a.cls[i] * 16 + a.cls[j] * 4 + a.cls[k]];
        }
    return a;
}

constexpr Alg ALG = make_alg();
constexpr int PN = ALG.P;

// ---- Per-row slot plan: group the 64 terms of output row j by w_gp column p.
struct RowPlan {
    signed char slot[64];
    signed char pofs[8];
    signed char first[64];
    int ns;
};

constexpr RowPlan make_plan(int j) {
    RowPlan r{};
    r.ns = 0;
    for (int s = 0; s < 8; ++s) r.pofs[s] = -1;
    for (int i = 0; i < 64; ++i) {
        int p = ALG.ptab[j][i];
        int s = 0;
        for (; s < r.ns; ++s)
            if (r.pofs[s] == p) break;
        r.first[i] = (s == r.ns) ? 1 : 0;
        if (s == r.ns) r.pofs[r.ns++] = (signed char)p;
        r.slot[i] = (signed char)s;
    }
    return r;
}

constexpr bool ns_ok() {
    for (int j = 0; j < 64; ++j)
        if (make_plan(j).ns > 8) return false;
    return true;
}
static_assert(ns_ok(), "row uses more than 8 distinct paths");

// ---- Scalar constexpr wrappers (device sees only folded integers).
template <int J, int I> struct GT {
    static constexpr int  k   = (int)ALG.ktab[J][I];
    static constexpr bool neg = ALG.sgn[J][I] != 0;
    static constexpr int  s   = (int)make_plan(J).slot[I];
    static constexpr bool fst = make_plan(J).first[I] != 0;
};
template <int J, int S> struct SP {
    static constexpr int p = (int)make_plan(J).pofs[S];
};
template <int J> struct RN {
    static constexpr int ns = make_plan(J).ns;
};
template <int I> struct CT {
    static constexpr int c = ALG.cls[I];
};
template <int Q> struct PP {
    static constexpr int cl = ALG.cls[2 * Q];
    static constexpr int ch = ALG.cls[2 * Q + 1];
};

constexpr bool pat_ok() {
    for (int q = 0; q < 32; ++q) {
        int cl = ALG.cls[2 * q], ch = ALG.cls[2 * q + 1];
        bool ok = (cl == 0 && ch == 0) || (cl == 0 && ch == 1) || (cl == 1 && ch == 1) ||
                  (cl == 1 && ch == 2) || (cl == 2 && ch == 2) || (cl == 3 && ch == 3);
        if (!ok) return false;
    }
    return true;
}
static_assert(pat_ok(), "unexpected adjacent class pattern");

static constexpr int NB = 256;   // batch
static constexpr int NF = 128;   // features
static constexpr int DV = 64;    // DIM
static constexpr int XS = 68;    // padded smem row stride (floats), 16B-aligned

// ---------------------------------------------------------------------------
// Packed f32x2 helpers (linear phase)
// ---------------------------------------------------------------------------

using u64 = unsigned long long;

__device__ __forceinline__ u64 fma2(u64 a, u64 b, u64 c) {
    u64 d;
    asm("fma.rn.f32x2 %0, %1, %2, %3;" : "=l"(d) : "l"(a), "l"(b), "l"(c));
    return d;
}

// wp order: [0]=(0,0) [1]=(0,1) [2]=(1,1) [3]=(1,2) [4]=(2,2) [5]=(3,3)
template <int CL, int CH>
__device__ __forceinline__ u64 selw(const u64* wp) {
    if constexpr (CL == 0 && CH == 0) return wp[0];
    else if constexpr (CL == 0 && CH == 1) return wp[1];
    else if constexpr (CL == 1 && CH == 1) return wp[2];
    else if constexpr (CL == 1 && CH == 2) return wp[3];
    else if constexpr (CL == 2 && CH == 2) return wp[4];
    else return wp[5];  // (3,3)
}

template <std::size_t... Ts>
__device__ __forceinline__ void lin_m2(u64* acc2, const u64* wp, const ulonglong2* xm,
                                       std::index_sequence<Ts...>) {
    ([&] {
        const ulonglong2 v = xm[Ts];
        acc2[2 * Ts]     = fma2(v.x, selw<PP<2 * (int)Ts>::cl,     PP<2 * (int)Ts>::ch>(wp),
                                acc2[2 * Ts]);
        acc2[2 * Ts + 1] = fma2(v.y, selw<PP<2 * (int)Ts + 1>::cl, PP<2 * (int)Ts + 1>::ch>(wp),
                                acc2[2 * Ts + 1]);
    }(), ...);
}

// ---------------------------------------------------------------------------
// Misc template helpers
// ---------------------------------------------------------------------------

template <std::size_t... Is>
__device__ __forceinline__ void sq_accum(float* sq, const float* acc, std::index_sequence<Is...>) {
    ((sq[CT<(int)Is>::c] = fmaf(acc[Is], acc[Is], sq[CT<(int)Is>::c])), ...);
}

template <std::size_t... Is>
__device__ __forceinline__ void xr_scale(float* xr, const float* acc, const float* inv,
                                         std::index_sequence<Is...>) {
    ((xr[Is] = acc[Is] * inv[CT<(int)Is>::c]), ...);
}

// ---------------------------------------------------------------------------
// GP phase: sign-folded slot accumulation (1 FFMA per term).
// ---------------------------------------------------------------------------

template <int J, int I>
__device__ __forceinline__ void gp_term(float* S, const float* xv, const float* xr) {
    const float xrk = GT<J, I>::neg ? -xr[GT<J, I>::k] : xr[GT<J, I>::k];
    if constexpr (GT<J, I>::fst)
        S[GT<J, I>::s] = xv[I] * xrk;
    else
        S[GT<J, I>::s] = fmaf(xv[I], xrk, S[GT<J, I>::s]);
}

template <int J, int S8>
__device__ __forceinline__ void gp_comb(float& acc, const float* S, const float* w) {
    if constexpr (S8 < RN<J>::ns) acc = fmaf(w[SP<J, S8>::p], S[S8], acc);
}

template <int J, std::size_t... Is>
__device__ __forceinline__ float gp_row(const float* xv, const float* xr, const float* w,
                                        std::index_sequence<Is...>) {
    float S[8];
    (gp_term<J, (int)Is>(S, xv, xr), ...);
    float acc = 0.f;
    gp_comb<J, 0>(acc, S, w); gp_comb<J, 1>(acc, S, w);
    gp_comb<J, 2>(acc, S, w); gp_comb<J, 3>(acc, S, w);
    gp_comb<J, 4>(acc, S, w); gp_comb<J, 5>(acc, S, w);
    gp_comb<J, 6>(acc, S, w); gp_comb<J, 7>(acc, S, w);
    return acc;
}

template <int G>
__device__ __forceinline__ void gp_group(float* __restrict__ orow, const float* xv,
                                         const float* xr, const float* w) {
    float4 v;
    v.x = gp_row<4 * G + 0>(xv, xr, w, std::make_index_sequence<64>{});
    v.y = gp_row<4 * G + 1>(xv, xr, w, std::make_index_sequence<64>{});
    v.z = gp_row<4 * G + 2>(xv, xr, w, std::make_index_sequence<64>{});
    v.w = gp_row<4 * G + 3>(xv, xr, w, std::make_index_sequence<64>{});
    *reinterpret_cast<float4*>(orow + 4 * G) = v;
}

template <std::size_t... Gs>
__device__ __forceinline__ void gp_all(float* __restrict__ orow, const float* xv, const float* xr,
                                       const float* w, std::index_sequence<Gs...>) {
    (gp_group<(int)Gs>(orow, xv, xr, w), ...);
}

// ---------------------------------------------------------------------------
// Scratch buffers
// ---------------------------------------------------------------------------

__device__ float4 g_wlt[NF * NF];                    // w_lin transposed: [m][n] float4
__device__ float2 g_xr[(size_t)NB * 32 * NF];        // xr transposed: [b][q][n], q = i/2 (8 MB)

__global__ void wlt_kernel(const float4* __restrict__ w) {
    int idx = blockIdx.x * 256 + threadIdx.x;        // 16384 float4 elements
    int n = idx >> 7;
    int m = idx & 127;
    g_wlt[m * NF + n] = w[idx];
}

// ---------------------------------------------------------------------------
// Kernel 1: linear + norm + gate -> g_xr.  CTA = b, 256 threads = (n, m-half).
// ---------------------------------------------------------------------------

__global__ void __launch_bounds__(256, 2)
lin_kernel(const float* __restrict__ x, const float* __restrict__ b_lin,
           const float* __restrict__ a_norm) {
    __shared__ __align__(16) float x_s[NF * XS];     // x tile, later reused as reduce buf

    const int b = blockIdx.x;
    const int tid = threadIdx.x;
    const int n = tid & 127;
    const int h = tid >> 7;

    // Stage x[b] into smem (coalesced, padded rows).
    {
        const float4* xg = reinterpret_cast<const float4*>(x + (size_t)b * NF * DV);
#pragma unroll
        for (int t = 0; t < 8; ++t) {
            int idx = t * 256 + tid;
            int m = idx >> 4, c = idx & 15;
            *reinterpret_cast<float4*>(x_s + m * XS + c * 4) = xg[idx];
        }
    }
    __syncthreads();

    // Each (n, h) accumulates over its 64 m's.
    u64 acc2[32];
#pragma unroll
    for (int q = 0; q < 32; ++q) acc2[q] = 0ull;

    const int m0 = h * 64;
#pragma unroll 4
    for (int mm = 0; mm < 64; ++mm) {
        const int m = m0 + mm;
        const float4 w4 = g_wlt[m * NF + n];
        u64 wp[6];
        asm("mov.b64 %0, {%1,%1};" : "=l"(wp[0]) : "f"(w4.x));
        asm("mov.b64 %0, {%1,%2};" : "=l"(wp[1]) : "f"(w4.x), "f"(w4.y));
        asm("mov.b64 %0, {%1,%1};" : "=l"(wp[2]) : "f"(w4.y));
        asm("mov.b64 %0, {%1,%2};" : "=l"(wp[3]) : "f"(w4.y), "f"(w4.z));
        asm("mov.b64 %0, {%1,%1};" : "=l"(wp[4]) : "f"(w4.z));
        asm("mov.b64 %0, {%1,%1};" : "=l"(wp[5]) : "f"(w4.w));
        const ulonglong2* xm = reinterpret_cast<const ulonglong2*>(x_s + m * XS);
        lin_m2(acc2, wp, xm, std::make_index_sequence<16>{});
    }

    float acc[DV];
#pragma unroll
    for (int q = 0; q < 32; ++q)
        asm("mov.b64 {%0,%1}, %2;" : "=f"(acc[2 * q]), "=f"(acc[2 * q + 1]) : "l"(acc2[q]));

    // Pair-reduce via smem (x_s is dead — reuse it, padded stride).
    __syncthreads();
    if (h == 1) {
#pragma unroll
        for (int t = 0; t < 16; ++t)
            *reinterpret_cast<float4*>(x_s + n * XS + 4 * t) =
                *reinterpret_cast<const float4*>(acc + 4 * t);
    }
    __syncthreads();

    if (h == 0) {
#pragma unroll
        for (int t = 0; t < 16; ++t) {
            float4 v = *reinterpret_cast<const float4*>(x_s + n * XS + 4 * t);
            acc[4 * t + 0] += v.x;
            acc[4 * t + 1] += v.y;
            acc[4 * t + 2] += v.z;
            acc[4 * t + 3] += v.w;
        }
        acc[0] += b_lin[n];

        float sq[4] = {0.f, 0.f, 0.f, 0.f};
        sq_accum(sq, acc, std::make_index_sequence<64>{});

        float inv[4];
#pragma unroll
        for (int c = 0; c < 4; ++c) {
            float nrm = sqrtf(sq[c]);
            float an = a_norm[n * 4 + c];
            float sig = 1.f / (1.f + expf(-an));
            float gate = fmaf(sig, nrm - 1.f, 1.f);
            inv[c] = 1.f / (gate + 1e-6f);
        }

        float xr[DV];
        xr_scale(xr, acc, inv, std::make_index_sequence<64>{});

        // Store transposed: g_xr[b][q][n] — coalesced STG.64 per q.
        float2* dst = g_xr + (size_t)b * 32 * NF + n;
#pragma unroll
        for (int q = 0; q < 32; ++q)
            dst[q * NF] = make_float2(xr[2 * q], xr[2 * q + 1]);
    }
}

// ---------------------------------------------------------------------------
// Kernel 2: geometric product.  CTA = b, 128 threads = n.
// ---------------------------------------------------------------------------

__global__ void __launch_bounds__(128, 2)
gp_kernel(const float* __restrict__ x, const float* __restrict__ w_gp,
          float* __restrict__ out) {
    __shared__ __align__(16) float xsg[NF * XS];     // x tile, later reused for out staging

    const int b = blockIdx.x;
    const int n = threadIdx.x;

    // Stage x[b] coalesced into smem.
    {
        const float4* xg = reinterpret_cast<const float4*>(x + (size_t)b * NF * DV);
#pragma unroll
        for (int t = 0; t < 16; ++t) {
            int idx = t * 128 + n;
            int m = idx >> 4, c = idx & 15;
            *reinterpret_cast<float4*>(xsg + m * XS + c * 4) = xg[idx];
        }
    }

    // xr row: coalesced float2 loads from transposed scratch.
    float xr[DV];
    {
        const float2* src = g_xr + (size_t)b * 32 * NF + n;
#pragma unroll
        for (int q = 0; q < 32; ++q) {
            float2 v = src[q * NF];
            xr[2 * q + 0] = v.x;
            xr[2 * q + 1] = v.y;
        }
    }

    // w_gp row (16 KB total, L2-resident across CTAs).
    float w[PN];
    {
        const float4* wg = reinterpret_cast<const float4*>(w_gp + (size_t)n * PN);
#pragma unroll
        for (int t = 0; t < PN / 4; ++t) {
            float4 v = wg[t];
            w[4 * t + 0] = v.x;
            w[4 * t + 1] = v.y;
            w[4 * t + 2] = v.z;
            w[4 * t + 3] = v.w;
        }
    }

    __syncthreads();

    // xv = x[b,n,:] from smem row n.
    float xv[DV];
#pragma unroll
    for (int t = 0; t < 16; ++t) {
        float4 v = *reinterpret_cast<const float4*>(xsg + n * XS + 4 * t);
        xv[4 * t + 0] = v.x;
        xv[4 * t + 1] = v.y;
        xv[4 * t + 2] = v.z;
        xv[4 * t + 3] = v.w;
    }
    __syncthreads();   // xsg about to be reused for output staging

    // GP into smem row (padded stride), then coalesced copy to gmem.
    gp_all(xsg + n * XS, xv, xr, w, std::make_index_sequence<16>{});
    __syncthreads();

    {
        float4* og = reinterpret_cast<float4*>(out + (size_t)b * NF * DV);
#pragma unroll
        for (int t = 0; t < 16; ++t) {
            int idx = t * 128 + n;
            int m = idx >> 4, c = idx & 15;
            og[idx] = *reinterpret_cast<const float4*>(xsg + m * XS + c * 4);
        }
    }
}

// ---------------------------------------------------------------------------

extern "C" void kernel_launch(void* const* d_in, const int* in_sizes, int n_in,
                              void* d_out, int out_size) {
    (void)in_sizes; (void)n_in; (void)out_size;
    const float* x      = (const float*)d_in[0];
    const float* w_gp   = (const float*)d_in[1];
    const float* w_lin  = (const float*)d_in[2];
    const float* b_lin  = (const float*)d_in[3];
    const float* a_norm = (const float*)d_in[4];
    float* out = (float*)d_out;

    wlt_kernel<<<64, 256>>>((const float4*)w_lin);
    lin_kernel<<<NB, 256>>>(x, b_lin, a_norm);
    gp_kernel<<<NB, 128>>>(x, w_gp, out);
}

// round 10
// speedup vs baseline: 1.1033x; 1.1033x over previous
#include <cuda_runtime.h>
#include <utility>
#include <cstddef>

// ============================================================================
// Compile-time Clifford algebra tables for N_GEN = 6 (DIM = 64).
// ============================================================================

struct Alg {
    int blade[64];
    int cls[64];
    signed char ktab[64][64];   // [j][i] -> k
    signed char sgn[64][64];    // [j][i] -> 1 if negative
    signed char ptab[64][64];   // [j][i] -> w_gp column p
    int P;
};

constexpr int popc6(int x) { int c = 0; for (int b = 0; b < 6; ++b) c += (x >> b) & 1; return c; }

constexpr Alg make_alg() {
    Alg a{};
    int idx = 0;
    for (int g = 0; g <= 6; ++g)
        for (int b = 0; b < 64; ++b)
            if (popc6(b) == g) a.blade[idx++] = b;
    int inv[64] = {};
    for (int i = 0; i < 64; ++i) inv[a.blade[i]] = i;
    for (int i = 0; i < 64; ++i) a.cls[i] = popc6(a.blade[i]) & 3;

    bool paths[64] = {};
    for (int i = 0; i < 64; ++i)
        for (int k = 0; k < 64; ++k) {
            int j = inv[a.blade[i] ^ a.blade[k]];
            paths[a.cls[i] * 16 + a.cls[j] * 4 + a.cls[k]] = true;
        }
    int pmap[64] = {};
    int P = 0;
    for (int t = 0; t < 64; ++t) pmap[t] = paths[t] ? P++ : -1;
    a.P = P;

    for (int j = 0; j < 64; ++j)
        for (int i = 0; i < 64; ++i) {
            int bi = a.blade[i], bj = a.blade[j];
            int bk = bi ^ bj;
            int k = inv[bk];
            a.ktab[j][i] = (signed char)k;
            int s = 0;
            int t = bi >> 1;
            while (t) { s += popc6(t & bk); t >>= 1; }
            a.sgn[j][i] = (signed char)(s & 1);
            a.ptab[j][i] = (signed char)pmap[a.cls[i] * 16 + a.cls[j] * 4 + a.cls[k]];
        }
    return a;
}

constexpr Alg ALG = make_alg();
constexpr int PN = ALG.P;

// ---- Per-row slot plan: group the 64 terms of output row j by w_gp column p.
struct RowPlan {
    signed char slot[64];
    signed char pofs[8];
    signed char first[64];
    int ns;
};

constexpr RowPlan make_plan(int j) {
    RowPlan r{};
    r.ns = 0;
    for (int s = 0; s < 8; ++s) r.pofs[s] = -1;
    for (int i = 0; i < 64; ++i) {
        int p = ALG.ptab[j][i];
        int s = 0;
        for (; s < r.ns; ++s)
            if (r.pofs[s] == p) break;
        r.first[i] = (s == r.ns) ? 1 : 0;
        if (s == r.ns) r.pofs[r.ns++] = (signed char)p;
        r.slot[i] = (signed char)s;
    }
    return r;
}

constexpr bool ns_ok() {
    for (int j = 0; j < 64; ++j)
        if (make_plan(j).ns > 8) return false;
    return true;
}
static_assert(ns_ok(), "row uses more than 8 distinct paths");

// ---- Scalar constexpr wrappers (device sees only folded integers).
template <int J, int I> struct GT {
    static constexpr int  k   = (int)ALG.ktab[J][I];
    static constexpr bool neg = ALG.sgn[J][I] != 0;
    static constexpr int  s   = (int)make_plan(J).slot[I];
    static constexpr bool fst = make_plan(J).first[I] != 0;
};
template <int J, int S> struct SP {
    static constexpr int p = (int)make_plan(J).pofs[S];
};
template <int J> struct RN {
    static constexpr int ns = make_plan(J).ns;
};
template <int I> struct CT {
    static constexpr int c = ALG.cls[I];
};
template <int Q> struct PP {
    static constexpr int cl = ALG.cls[2 * Q];
    static constexpr int ch = ALG.cls[2 * Q + 1];
};

constexpr bool pat_ok() {
    for (int q = 0; q < 32; ++q) {
        int cl = ALG.cls[2 * q], ch = ALG.cls[2 * q + 1];
        bool ok = (cl == 0 && ch == 0) || (cl == 0 && ch == 1) || (cl == 1 && ch == 1) ||
                  (cl == 1 && ch == 2) || (cl == 2 && ch == 2) || (cl == 3 && ch == 3);
        if (!ok) return false;
    }
    return true;
}
static_assert(pat_ok(), "unexpected adjacent class pattern");

static constexpr int NB = 256;   // batch
static constexpr int NF = 128;   // features
static constexpr int DV = 64;    // DIM
static constexpr int XS = 68;    // padded smem row stride (floats), 16B-aligned

// ---------------------------------------------------------------------------
// Packed f32x2 helpers (linear phase)
// ---------------------------------------------------------------------------

using u64 = unsigned long long;

__device__ __forceinline__ u64 fma2(u64 a, u64 b, u64 c) {
    u64 d;
    asm("fma.rn.f32x2 %0, %1, %2, %3;" : "=l"(d) : "l"(a), "l"(b), "l"(c));
    return d;
}

// wp order: [0]=(0,0) [1]=(0,1) [2]=(1,1) [3]=(1,2) [4]=(2,2) [5]=(3,3)
template <int CL, int CH>
__device__ __forceinline__ u64 selw(const u64* wp) {
    if constexpr (CL == 0 && CH == 0) return wp[0];
    else if constexpr (CL == 0 && CH == 1) return wp[1];
    else if constexpr (CL == 1 && CH == 1) return wp[2];
    else if constexpr (CL == 1 && CH == 2) return wp[3];
    else if constexpr (CL == 2 && CH == 2) return wp[4];
    else return wp[5];  // (3,3)
}

template <std::size_t... Ts>
__device__ __forceinline__ void lin_m2(u64* acc2, const u64* wp, const ulonglong2* xm,
                                       std::index_sequence<Ts...>) {
    ([&] {
        const ulonglong2 v = xm[Ts];
        acc2[2 * Ts]     = fma2(v.x, selw<PP<2 * (int)Ts>::cl,     PP<2 * (int)Ts>::ch>(wp),
                                acc2[2 * Ts]);
        acc2[2 * Ts + 1] = fma2(v.y, selw<PP<2 * (int)Ts + 1>::cl, PP<2 * (int)Ts + 1>::ch>(wp),
                                acc2[2 * Ts + 1]);
    }(), ...);
}

// ---------------------------------------------------------------------------
// Misc template helpers
// ---------------------------------------------------------------------------

template <std::size_t... Is>
__device__ __forceinline__ void sq_accum(float* sq, const float* acc, std::index_sequence<Is...>) {
    ((sq[CT<(int)Is>::c] = fmaf(acc[Is], acc[Is], sq[CT<(int)Is>::c])), ...);
}

template <std::size_t... Is>
__device__ __forceinline__ void xr_scale(float* xr, const float* acc, const float* inv,
                                         std::index_sequence<Is...>) {
    ((xr[Is] = acc[Is] * inv[CT<(int)Is>::c]), ...);
}

// ---------------------------------------------------------------------------
// GP phase: sign-folded slot accumulation (1 FFMA per term).
// ---------------------------------------------------------------------------

template <int J, int I>
__device__ __forceinline__ void gp_term(float* S, const float* xv, const float* xr) {
    const float xrk = GT<J, I>::neg ? -xr[GT<J, I>::k] : xr[GT<J, I>::k];
    if constexpr (GT<J, I>::fst)
        S[GT<J, I>::s] = xv[I] * xrk;
    else
        S[GT<J, I>::s] = fmaf(xv[I], xrk, S[GT<J, I>::s]);
}

template <int J, int S8>
__device__ __forceinline__ void gp_comb(float& acc, const float* S, const float* w) {
    if constexpr (S8 < RN<J>::ns) acc = fmaf(w[SP<J, S8>::p], S[S8], acc);
}

template <int J, std::size_t... Is>
__device__ __forceinline__ float gp_row(const float* xv, const float* xr, const float* w,
                                        std::index_sequence<Is...>) {
    float S[8];
    (gp_term<J, (int)Is>(S, xv, xr), ...);
    float acc = 0.f;
    gp_comb<J, 0>(acc, S, w); gp_comb<J, 1>(acc, S, w);
    gp_comb<J, 2>(acc, S, w); gp_comb<J, 3>(acc, S, w);
    gp_comb<J, 4>(acc, S, w); gp_comb<J, 5>(acc, S, w);
    gp_comb<J, 6>(acc, S, w); gp_comb<J, 7>(acc, S, w);
    return acc;
}

template <int G>
__device__ __forceinline__ void gp_group(float* __restrict__ orow, const float* xv,
                                         const float* xr, const float* w) {
    float4 v;
    v.x = gp_row<4 * G + 0>(xv, xr, w, std::make_index_sequence<64>{});
    v.y = gp_row<4 * G + 1>(xv, xr, w, std::make_index_sequence<64>{});
    v.z = gp_row<4 * G + 2>(xv, xr, w, std::make_index_sequence<64>{});
    v.w = gp_row<4 * G + 3>(xv, xr, w, std::make_index_sequence<64>{});
    *reinterpret_cast<float4*>(orow + 4 * G) = v;
}

template <std::size_t... Gs>
__device__ __forceinline__ void gp_all(float* __restrict__ orow, const float* xv, const float* xr,
                                       const float* w, std::index_sequence<Gs...>) {
    (gp_group<(int)Gs>(orow, xv, xr, w), ...);
}

// ---------------------------------------------------------------------------
// Transposed w_lin scratch: [m][n] float4, built by a tiled (coalesced both
// sides) transpose: 64 CTAs x 256 threads, 16x16-float4 tiles.
// ---------------------------------------------------------------------------

__device__ float4 g_wlt[NF * NF];

__global__ void wlt_kernel(const float4* __restrict__ w) {
    __shared__ float4 t[16][17];   // +1 pad kills bank conflicts on transposed read
    const int mb = blockIdx.x & 7;       // 8 tiles along m
    const int nb = blockIdx.x >> 3;      // 8 tiles along n
    const int tm = threadIdx.x & 15;
    const int tn = threadIdx.x >> 4;

    // Read w_lin[n][m] coalesced in m.
    t[tn][tm] = w[(nb * 16 + tn) * NF + (mb * 16 + tm)];
    __syncthreads();
    // Write g_wlt[m][n] coalesced in n.
    g_wlt[(mb * 16 + tn) * NF + (nb * 16 + tm)] = t[tm][tn];
}

// ---------------------------------------------------------------------------
// Fused kernel: one CTA per batch element b, one thread per feature n.
// ---------------------------------------------------------------------------

__global__ void __launch_bounds__(128, 2)
qgp_kernel(const float* __restrict__ x, const float* __restrict__ w_gp,
           const float* __restrict__ b_lin, const float* __restrict__ a_norm,
           float* __restrict__ out) {
    __shared__ __align__(16) float x_s[NF * XS];   // x tile; reused for output staging

    const int b = blockIdx.x;
    const int n = threadIdx.x;

    // Stage x[b] into smem (coalesced gmem reads, padded smem rows).
    {
        const float4* xg = reinterpret_cast<const float4*>(x + (size_t)b * NF * DV);
#pragma unroll
        for (int t = 0; t < 16; ++t) {
            int idx = t * 128 + n;
            int m = idx >> 4, c = idx & 15;
            *reinterpret_cast<float4*>(x_s + m * XS + c * 4) = xg[idx];
        }
    }
    __syncthreads();

    // ---- Linear phase (packed f32x2): xr[n,i] = sum_m x[b,m,i] * w_lin[n,m,cls[i]] ----
    u64 acc2[32];
#pragma unroll
    for (int q = 0; q < 32; ++q) acc2[q] = 0ull;

#pragma unroll 4
    for (int m = 0; m < NF; ++m) {
        const float4 w4 = g_wlt[m * NF + n];   // coalesced across lanes, L2-resident
        u64 wp[6];
        asm("mov.b64 %0, {%1,%1};" : "=l"(wp[0]) : "f"(w4.x));
        asm("mov.b64 %0, {%1,%2};" : "=l"(wp[1]) : "f"(w4.x), "f"(w4.y));
        asm("mov.b64 %0, {%1,%1};" : "=l"(wp[2]) : "f"(w4.y));
        asm("mov.b64 %0, {%1,%2};" : "=l"(wp[3]) : "f"(w4.y), "f"(w4.z));
        asm("mov.b64 %0, {%1,%1};" : "=l"(wp[4]) : "f"(w4.z));
        asm("mov.b64 %0, {%1,%1};" : "=l"(wp[5]) : "f"(w4.w));
        const ulonglong2* xm = reinterpret_cast<const ulonglong2*>(x_s + m * XS);
        lin_m2(acc2, wp, xm, std::make_index_sequence<16>{});
    }

    float acc[DV];
#pragma unroll
    for (int q = 0; q < 32; ++q)
        asm("mov.b64 {%0,%1}, %2;" : "=f"(acc[2 * q]), "=f"(acc[2 * q + 1]) : "l"(acc2[q]));

    acc[0] += b_lin[n];

    // ---- Norms per class, sigmoid gate, scale ----
    float sq[4] = {0.f, 0.f, 0.f, 0.f};
    sq_accum(sq, acc, std::make_index_sequence<64>{});

    float inv[4];
#pragma unroll
    for (int c = 0; c < 4; ++c) {
        float nrm = sqrtf(sq[c]);
        float an = a_norm[n * 4 + c];
        float sig = 1.f / (1.f + expf(-an));
        float gate = fmaf(sig, nrm - 1.f, 1.f);
        inv[c] = 1.f / (gate + 1e-6f);
    }

    float xr[DV];
    xr_scale(xr, acc, inv, std::make_index_sequence<64>{});

    // ---- xv = x[b,n,:] straight from smem (row m == n) ----
    float xv[DV];
#pragma unroll
    for (int t = 0; t < 16; ++t) {
        float4 v = *reinterpret_cast<const float4*>(x_s + n * XS + 4 * t);
        xv[4 * t + 0] = v.x;
        xv[4 * t + 1] = v.y;
        xv[4 * t + 2] = v.z;
        xv[4 * t + 3] = v.w;
    }

    // ---- w_gp row (16 KB total, L2-resident across CTAs) ----
    float w[PN];
    {
        const float4* wg = reinterpret_cast<const float4*>(w_gp + (size_t)n * PN);
#pragma unroll
        for (int t = 0; t < PN / 4; ++t) {
            float4 v = wg[t];
            w[4 * t + 0] = v.x;
            w[4 * t + 1] = v.y;
            w[4 * t + 2] = v.z;
            w[4 * t + 3] = v.w;
        }
    }

    __syncthreads();   // everyone done reading x_s; reuse it for output staging

    // ---- Geometric product into smem row, then coalesced copy to gmem ----
    gp_all(x_s + n * XS, xv, xr, w, std::make_index_sequence<16>{});
    __syncthreads();

    {
        float4* og = reinterpret_cast<float4*>(out + (size_t)b * NF * DV);
#pragma unroll
        for (int t = 0; t < 16; ++t) {
            int idx = t * 128 + n;
            int m = idx >> 4, c = idx & 15;
            og[idx] = *reinterpret_cast<const float4*>(x_s + m * XS + c * 4);
        }
    }
}

// ---------------------------------------------------------------------------

extern "C" void kernel_launch(void* const* d_in, const int* in_sizes, int n_in,
                              void* d_out, int out_size) {
    (void)in_sizes; (void)n_in; (void)out_size;
    const float* x      = (const float*)d_in[0];
    const float* w_gp   = (const float*)d_in[1];
    const float* w_lin  = (const float*)d_in[2];
    const float* b_lin  = (const float*)d_in[3];
    const float* a_norm = (const float*)d_in[4];
    float* out = (float*)d_out;

    wlt_kernel<<<64, 256>>>((const float4*)w_lin);
    qgp_kernel<<<NB, NF>>>(x, w_gp, b_lin, a_norm, out);
}